// round 7
// baseline (speedup 1.0000x reference)
#include <cuda_runtime.h>
#include <cuda_fp16.h>
#include <cstdint>

// ---------------------------------------------------------------------------
// EdgeConv (mlp_layer=0, aggregate=max), restructured:
//   t      = feat @ theta_w                      [N, 64]
//   base   = t + feat @ phi_w + theta_b + phi_b  [N, 64]   (written to d_out)
//   out[v] = base[v] - min_k t[nbr[v,k]]         (per-feature min)
//
// GEMM: legacy tensor cores (mma.sync m16n8k16 fp16), 2-pass split:
//   t ~= Ahi*Bhi + Alo*Bhi   (B single fp16; dropped terms ~2e-4 rel)
// Gather: t stored as fp16 -> halves the L2-bound gather stream.
// ---------------------------------------------------------------------------

#define F_DIM 64
#define N_MAX 120000

__device__ __half g_t16[(size_t)N_MAX * F_DIM];   // fp16 t for the gather

// ============================= PTX helpers =================================
__device__ __forceinline__ uint32_t smem_u32(const void* p) {
    uint32_t a;
    asm("{ .reg .u64 tmp; cvta.to.shared.u64 tmp, %1; cvt.u32.u64 %0, tmp; }"
        : "=r"(a) : "l"(p));
    return a;
}

__device__ __forceinline__ void ldsm_x4(uint32_t* r, uint32_t addr) {
    asm volatile("ldmatrix.sync.aligned.m8n8.x4.shared.b16 {%0,%1,%2,%3}, [%4];"
                 : "=r"(r[0]), "=r"(r[1]), "=r"(r[2]), "=r"(r[3]) : "r"(addr));
}

__device__ __forceinline__ void mma16816(float* c, const uint32_t* a,
                                         const uint32_t* b) {
    asm volatile(
        "mma.sync.aligned.m16n8k16.row.col.f32.f16.f16.f32 "
        "{%0,%1,%2,%3}, {%4,%5,%6,%7}, {%8,%9}, {%0,%1,%2,%3};"
        : "+f"(c[0]), "+f"(c[1]), "+f"(c[2]), "+f"(c[3])
        : "r"(a[0]), "r"(a[1]), "r"(a[2]), "r"(a[3]), "r"(b[0]), "r"(b[1]));
}

// fp16 hi/lo split of two floats -> packed hi word + lo word
__device__ __forceinline__ uint32_t pack_hilo(float x, float y,
                                              uint32_t& lo_out) {
    __half hx = __float2half_rn(x);
    __half hy = __float2half_rn(y);
    __half lx = __float2half_rn(x - __half2float(hx));
    __half ly = __float2half_rn(y - __half2float(hy));
    lo_out = (uint32_t)__half_as_ushort(lx) |
             ((uint32_t)__half_as_ushort(ly) << 16);
    return (uint32_t)__half_as_ushort(hx) |
           ((uint32_t)__half_as_ushort(hy) << 16);
}

__device__ __forceinline__ uint32_t pack_hi(float x, float y) {
    __half hx = __float2half_rn(x);
    __half hy = __float2half_rn(y);
    return (uint32_t)__half_as_ushort(hx) |
           ((uint32_t)__half_as_ushort(hy) << 16);
}

// SMEM layout (dynamic, bytes). Rows padded to 72 fp16 = 144 B (ldmatrix
// conflict-free: 8 rows x 144 B hit 8 distinct 16B bank groups).
#define SM_AH 0
#define SM_AL 9216
#define SM_BH 18432
#define SM_BYTES 36864

// ============================ GEMM kernel ==================================
// CTA: 64 rows x full N=128 ([theta|phi]). 8 warps: wm=(wid&1)*32,
// wn=(wid>>1)*16. Warp owns theta cols wn..wn+15 and phi cols 64+wn..64+wn+15
// -> t and base combine in registers.
__global__ __launch_bounds__(256, 4)
void gemm_mma_kernel(const float* __restrict__ feat,
                     const float* __restrict__ theta_w,
                     const float* __restrict__ theta_b,
                     const float* __restrict__ phi_w,
                     const float* __restrict__ phi_b,
                     float* __restrict__ out,
                     int n)
{
    extern __shared__ char sm[];
    const uint32_t sbase = smem_u32(sm);
    const int tid = threadIdx.x;
    const int rb  = blockIdx.x * 64;

    // ---- stage A: feat[rb..rb+63][0..63] -> fp16 hi/lo (coalesced f4) -----
#pragma unroll
    for (int p = 0; p < 4; p++) {
        int idx = tid + p * 256;         // 0..1023
        int c4  = idx & 15;              // float4 column group
        int row = idx >> 4;              // 0..63
        float4 f = make_float4(0.f, 0.f, 0.f, 0.f);
        int gr = rb + row;
        if (gr < n) f = *(const float4*)&feat[(size_t)gr * F_DIM + c4 * 4];
        uint32_t l0, l1;
        uint32_t h0 = pack_hilo(f.x, f.y, l0);
        uint32_t h1 = pack_hilo(f.z, f.w, l1);
        uint32_t off = row * 144 + c4 * 8;
        *(uint2*)(sm + SM_AH + off) = make_uint2(h0, h1);
        *(uint2*)(sm + SM_AL + off) = make_uint2(l0, l1);
    }

    // ---- stage B (hi only): B[nrow][k] = w[k][nrow]; nrow<64 theta else phi
#pragma unroll
    for (int p = 0; p < 8; p++) {
        int idx  = tid + p * 256;        // 0..2047
        int c4   = idx & 15;             // k group of 4
        int nrow = idx >> 4;             // 0..127
        const float* w = (nrow < 64) ? theta_w : phi_w;
        int nc = nrow & 63;
        float v0 = w[(c4 * 4 + 0) * F_DIM + nc];
        float v1 = w[(c4 * 4 + 1) * F_DIM + nc];
        float v2 = w[(c4 * 4 + 2) * F_DIM + nc];
        float v3 = w[(c4 * 4 + 3) * F_DIM + nc];
        uint32_t off = nrow * 144 + c4 * 8;
        *(uint2*)(sm + SM_BH + off) = make_uint2(pack_hi(v0, v1),
                                                 pack_hi(v2, v3));
    }
    __syncthreads();

    const int wid  = tid >> 5;
    const int lane = tid & 31;
    const int wm   = (wid & 1) * 32;
    const int wn   = (wid >> 1) * 16;
    const int li   = lane & 7;
    const int lg   = lane >> 3;

    float accT[2][2][4], accP[2][2][4];
#pragma unroll
    for (int mt = 0; mt < 2; mt++)
#pragma unroll
        for (int nt = 0; nt < 2; nt++)
#pragma unroll
            for (int j = 0; j < 4; j++) {
                accT[mt][nt][j] = 0.f;
                accP[mt][nt][j] = 0.f;
            }

#pragma unroll
    for (int p = 0; p < 2; p++) {
        const uint32_t aoff = p ? SM_AL : SM_AH;
#pragma unroll
        for (int ks = 0; ks < 4; ks++) {
            const int k0 = ks * 16;
            uint32_t a[2][4];
#pragma unroll
            for (int mt = 0; mt < 2; mt++) {
                int row = wm + mt * 16 + li + (lg & 1) * 8;
                int col = k0 + (lg >> 1) * 8;
                ldsm_x4(a[mt], sbase + aoff + row * 144 + col * 2);
            }
            uint32_t bT[2][2], bP[2][2];
            {
                int row = wn + li + (lg >> 1) * 8;
                int col = k0 + (lg & 1) * 8;
                uint32_t r[4];
                ldsm_x4(r, sbase + SM_BH + row * 144 + col * 2);
                bT[0][0] = r[0]; bT[0][1] = r[1];
                bT[1][0] = r[2]; bT[1][1] = r[3];
                ldsm_x4(r, sbase + SM_BH + (64 + row) * 144 + col * 2);
                bP[0][0] = r[0]; bP[0][1] = r[1];
                bP[1][0] = r[2]; bP[1][1] = r[3];
            }
#pragma unroll
            for (int mt = 0; mt < 2; mt++)
#pragma unroll
                for (int nt = 0; nt < 2; nt++) {
                    mma16816(accT[mt][nt], a[mt], bT[nt]);
                    mma16816(accP[mt][nt], a[mt], bP[nt]);
                }
        }
    }

    // ---- epilogue: direct register combine + store -------------------------
#pragma unroll
    for (int mt = 0; mt < 2; mt++) {
        int r0 = rb + wm + mt * 16 + (lane >> 2);
#pragma unroll
        for (int nt = 0; nt < 2; nt++) {
            int col = wn + nt * 8 + 2 * (lane & 3);
            float b0 = theta_b[col]     + phi_b[col];
            float b1 = theta_b[col + 1] + phi_b[col + 1];
            if (r0 < n) {
                size_t o = (size_t)r0 * F_DIM + col;
                float t0 = accT[mt][nt][0], t1 = accT[mt][nt][1];
                *(__half2*)&g_t16[o] = __floats2half2_rn(t0, t1);
                *(float2*)&out[o] = make_float2(t0 + accP[mt][nt][0] + b0,
                                                t1 + accP[mt][nt][1] + b1);
            }
            int r1 = r0 + 8;
            if (r1 < n) {
                size_t o = (size_t)r1 * F_DIM + col;
                float t2 = accT[mt][nt][2], t3 = accT[mt][nt][3];
                *(__half2*)&g_t16[o] = __floats2half2_rn(t2, t3);
                *(float2*)&out[o] = make_float2(t2 + accP[mt][nt][2] + b0,
                                                t3 + accP[mt][nt][3] + b1);
            }
        }
    }
}

// ---------------------------------------------------------------------------
// Kernel 2: gather-min over fp16 t. One warp per node; lane owns 2 features
// (one half2) -> warp reads 128 B per neighbor row. 32-bit offset math.
// Index dtype (int64 vs int32) detected per-warp via ballot on first 32 words.
// ---------------------------------------------------------------------------
__global__ __launch_bounds__(256)
void gather_min_kernel(const void* __restrict__ nbr_raw,
                       float* __restrict__ out,
                       int n, int K)
{
    const int lane = threadIdx.x & 31;

    unsigned int probe = ((const unsigned int*)nbr_raw)[lane];
    bool oddzero = ((lane & 1) == 0) || (probe == 0u);
    const bool is64 = (__ballot_sync(0xFFFFFFFFu, oddzero) == 0xFFFFFFFFu);

    int w = (int)((blockIdx.x * (long long)blockDim.x + threadIdx.x) >> 5);
    if (w >= n) return;

    const __half2* t2 = (const __half2*)g_t16;
    __half2 m = __float2half2_rn(65504.f);

    if (K == 16) {
        int u[16];
        if (is64) {
            const longlong2* nb = (const longlong2*)((const long long*)nbr_raw
                                                     + (size_t)w * 16);
#pragma unroll
            for (int j = 0; j < 8; j++) {
                longlong2 p = __ldg(&nb[j]);
                u[2 * j]     = (int)p.x;
                u[2 * j + 1] = (int)p.y;
            }
        } else {
            const int4* nb = (const int4*)((const int*)nbr_raw + (size_t)w * 16);
#pragma unroll
            for (int j = 0; j < 4; j++) {
                int4 p = __ldg(&nb[j]);
                u[4 * j]     = p.x;
                u[4 * j + 1] = p.y;
                u[4 * j + 2] = p.z;
                u[4 * j + 3] = p.w;
            }
        }
#pragma unroll
        for (int j = 0; j < 16; j++) {
            __half2 v = __ldg(&t2[u[j] * 32 + lane]);
            m = __hmin2(m, v);
        }
    } else {
        for (int j = 0; j < K; j++) {
            int u = is64 ? (int)((const long long*)nbr_raw)[(size_t)w * K + j]
                         : ((const int*)nbr_raw)[(size_t)w * K + j];
            __half2 v = __ldg(&t2[u * 32 + lane]);
            m = __hmin2(m, v);
        }
    }

    float2 mf = __half22float2(m);
    float2* out2 = (float2*)out;
    size_t o = (size_t)w * 32 + lane;
    float2 b = out2[o];
    b.x -= mf.x;
    b.y -= mf.y;
    out2[o] = b;
}

// ============================== launch =====================================
extern "C" void kernel_launch(void* const* d_in, const int* in_sizes, int n_in,
                              void* d_out, int out_size)
{
    const float* feat    = (const float*)d_in[0];
    const void*  nbr     = d_in[1];
    const float* theta_w = (const float*)d_in[2];
    const float* theta_b = (const float*)d_in[3];
    const float* phi_w   = (const float*)d_in[4];
    const float* phi_b   = (const float*)d_in[5];
    float* out = (float*)d_out;

    const int n = in_sizes[0] / F_DIM;     // number of nodes
    const int K = in_sizes[1] / n;         // neighbors per node (=16)

    static int smem_set = 0;
    if (!smem_set) {
        cudaFuncSetAttribute(gemm_mma_kernel,
                             cudaFuncAttributeMaxDynamicSharedMemorySize,
                             SM_BYTES);
        smem_set = 1;
    }

    int g1 = (n + 63) / 64;
    gemm_mma_kernel<<<g1, 256, SM_BYTES>>>(feat, theta_w, theta_b, phi_w,
                                           phi_b, out, n);

    long long total_threads = (long long)n * 32;
    int g2 = (int)((total_threads + 255) / 256);
    gather_min_kernel<<<g2, 256>>>(nbr, out, n, K);
}

// round 8
// speedup vs baseline: 1.5558x; 1.5558x over previous
#include <cuda_runtime.h>
#include <cuda_fp16.h>
#include <cstdint>

// ---------------------------------------------------------------------------
// EdgeConv (mlp_layer=0, aggregate=max), restructured:
//   t      = feat @ theta_w                      [N, 64]
//   base   = t + feat @ phi_w + theta_b + phi_b  [N, 64]   (written to d_out)
//   out[v] = base[v] - min_k t[nbr[v,k]]         (per-feature min)
//
// GEMM: mma.sync m16n8k16 fp16, 2-pass split (t ~= (Ahi+Alo)*Bhi).
// B is staged COALESCED as fp32 [k][c] and fragments are built via
// conflict-free LDS + cvt (the old [n][k] transpose staging was 8x
// sector-amplified and was the hidden 40us floor).
// Gather: t stored as fp16 -> halves the L2-bound gather stream.
// ---------------------------------------------------------------------------

#define F_DIM 64
#define N_MAX 120000

__device__ __half g_t16[(size_t)N_MAX * F_DIM];   // fp16 t for the gather

// ============================= PTX helpers =================================
__device__ __forceinline__ uint32_t smem_u32(const void* p) {
    uint32_t a;
    asm("{ .reg .u64 tmp; cvta.to.shared.u64 tmp, %1; cvt.u32.u64 %0, tmp; }"
        : "=r"(a) : "l"(p));
    return a;
}

__device__ __forceinline__ void ldsm_x4(uint32_t* r, uint32_t addr) {
    asm volatile("ldmatrix.sync.aligned.m8n8.x4.shared.b16 {%0,%1,%2,%3}, [%4];"
                 : "=r"(r[0]), "=r"(r[1]), "=r"(r[2]), "=r"(r[3]) : "r"(addr));
}

__device__ __forceinline__ void mma16816(float* c, const uint32_t* a,
                                         const uint32_t* b) {
    asm volatile(
        "mma.sync.aligned.m16n8k16.row.col.f32.f16.f16.f32 "
        "{%0,%1,%2,%3}, {%4,%5,%6,%7}, {%8,%9}, {%0,%1,%2,%3};"
        : "+f"(c[0]), "+f"(c[1]), "+f"(c[2]), "+f"(c[3])
        : "r"(a[0]), "r"(a[1]), "r"(a[2]), "r"(a[3]), "r"(b[0]), "r"(b[1]));
}

// fp16 hi/lo split of two floats -> packed hi word + lo word
__device__ __forceinline__ uint32_t pack_hilo(float x, float y,
                                              uint32_t& lo_out) {
    __half hx = __float2half_rn(x);
    __half hy = __float2half_rn(y);
    __half lx = __float2half_rn(x - __half2float(hx));
    __half ly = __float2half_rn(y - __half2float(hy));
    lo_out = (uint32_t)__half_as_ushort(lx) |
             ((uint32_t)__half_as_ushort(ly) << 16);
    return (uint32_t)__half_as_ushort(hx) |
           ((uint32_t)__half_as_ushort(hy) << 16);
}

__device__ __forceinline__ uint32_t pack_f16x2(float x, float y) {
    __half2 h = __floats2half2_rn(x, y);
    return *(uint32_t*)&h;
}

// SMEM layout (dynamic, bytes):
//   sAH/sAL: 64 rows x 72 fp16 (144 B rows; ldmatrix conflict-free)
//   sB32:    64 k-rows x 132 fp32 (528 B rows; c<64 theta, c>=64 phi)
#define SM_AH  0
#define SM_AL  9216
#define SM_B32 18432
#define SM_BYTES (18432 + 64 * 132 * 4)   // 52224

// ============================ GEMM kernel ==================================
// CTA: 64 rows x full N=128 ([theta|phi]). 8 warps: wm=(wid&1)*32,
// wn=(wid>>1)*16. Warp owns theta cols wn..wn+15 and phi cols 64+wn..64+wn+15
// -> t and base combine in registers.
__global__ __launch_bounds__(256, 4)
void gemm_mma_kernel(const float* __restrict__ feat,
                     const float* __restrict__ theta_w,
                     const float* __restrict__ theta_b,
                     const float* __restrict__ phi_w,
                     const float* __restrict__ phi_b,
                     float* __restrict__ out,
                     int n)
{
    extern __shared__ char sm[];
    const uint32_t sbase = smem_u32(sm);
    float* sB32 = (float*)(sm + SM_B32);     // [k][132]
    const int tid = threadIdx.x;
    const int rb  = blockIdx.x * 64;

    // ---- stage A: feat[rb..rb+63][0..63] -> fp16 hi/lo (coalesced f4) -----
#pragma unroll
    for (int p = 0; p < 4; p++) {
        int idx = tid + p * 256;         // 0..1023
        int c4  = idx & 15;              // float4 column group
        int row = idx >> 4;              // 0..63
        float4 f = make_float4(0.f, 0.f, 0.f, 0.f);
        int gr = rb + row;
        if (gr < n) f = *(const float4*)&feat[(size_t)gr * F_DIM + c4 * 4];
        uint32_t l0, l1;
        uint32_t h0 = pack_hilo(f.x, f.y, l0);
        uint32_t h1 = pack_hilo(f.z, f.w, l1);
        uint32_t off = row * 144 + c4 * 8;
        *(uint2*)(sm + SM_AH + off) = make_uint2(h0, h1);
        *(uint2*)(sm + SM_AL + off) = make_uint2(l0, l1);
    }

    // ---- stage B fp32 COALESCED: sB32[k][c] = w[k][c] (c fastest) ---------
#pragma unroll
    for (int p = 0; p < 8; p++) {
        int idx = tid + p * 256;         // 0..2047 float4 groups
        int hsel = idx >> 10;            // 0 theta, 1 phi
        int f4   = idx & 1023;
        int k    = f4 >> 4;              // 0..63
        int c4   = f4 & 15;              // 0..15
        const float* w = hsel ? phi_w : theta_w;
        float4 v = *(const float4*)&w[k * F_DIM + c4 * 4];
        *(float4*)&sB32[k * 132 + hsel * 64 + c4 * 4] = v;
    }
    __syncthreads();

    const int wid  = tid >> 5;
    const int lane = tid & 31;
    const int wm   = (wid & 1) * 32;
    const int wn   = (wid >> 1) * 16;
    const int li   = lane & 7;
    const int lg   = lane >> 3;

    float accT[2][2][4], accP[2][2][4];
#pragma unroll
    for (int mt = 0; mt < 2; mt++)
#pragma unroll
        for (int nt = 0; nt < 2; nt++)
#pragma unroll
            for (int j = 0; j < 4; j++) {
                accT[mt][nt][j] = 0.f;
                accP[mt][nt][j] = 0.f;
            }

#pragma unroll
    for (int ks = 0; ks < 4; ks++) {
        const int k0 = ks * 16;
        // ---- build B fragments from fp32 smem (conflict-free LDS) --------
        // canonical m16n8k16 B frag: b0 = B[k0+2(lane&3)][n], B[..+1][n]
        //                            b1 = rows +8 ; n = n0 + lane/4
        const int kr = k0 + 2 * (lane & 3);
        const int nc = lane >> 2;
        uint32_t bT[2][2], bP[2][2];
#pragma unroll
        for (int nt = 0; nt < 2; nt++) {
            const float* colT = &sB32[wn + nt * 8 + nc];
            const float* colP = colT + 64;
            bT[nt][0] = pack_f16x2(colT[kr * 132],       colT[(kr + 1) * 132]);
            bT[nt][1] = pack_f16x2(colT[(kr + 8) * 132], colT[(kr + 9) * 132]);
            bP[nt][0] = pack_f16x2(colP[kr * 132],       colP[(kr + 1) * 132]);
            bP[nt][1] = pack_f16x2(colP[(kr + 8) * 132], colP[(kr + 9) * 132]);
        }
        // ---- two A passes (hi, lo) share the B fragments ------------------
#pragma unroll
        for (int p = 0; p < 2; p++) {
            const uint32_t aoff = p ? SM_AL : SM_AH;
            uint32_t a[2][4];
#pragma unroll
            for (int mt = 0; mt < 2; mt++) {
                int row = wm + mt * 16 + li + (lg & 1) * 8;
                int col = k0 + (lg >> 1) * 8;
                ldsm_x4(a[mt], sbase + aoff + row * 144 + col * 2);
            }
#pragma unroll
            for (int mt = 0; mt < 2; mt++)
#pragma unroll
                for (int nt = 0; nt < 2; nt++) {
                    mma16816(accT[mt][nt], a[mt], bT[nt]);
                    mma16816(accP[mt][nt], a[mt], bP[nt]);
                }
        }
    }

    // ---- epilogue: direct register combine + store -------------------------
#pragma unroll
    for (int mt = 0; mt < 2; mt++) {
        int r0 = rb + wm + mt * 16 + (lane >> 2);
#pragma unroll
        for (int nt = 0; nt < 2; nt++) {
            int col = wn + nt * 8 + 2 * (lane & 3);
            float b0 = theta_b[col]     + phi_b[col];
            float b1 = theta_b[col + 1] + phi_b[col + 1];
            if (r0 < n) {
                size_t o = (size_t)r0 * F_DIM + col;
                float t0 = accT[mt][nt][0], t1 = accT[mt][nt][1];
                *(__half2*)&g_t16[o] = __floats2half2_rn(t0, t1);
                *(float2*)&out[o] = make_float2(t0 + accP[mt][nt][0] + b0,
                                                t1 + accP[mt][nt][1] + b1);
            }
            int r1 = r0 + 8;
            if (r1 < n) {
                size_t o = (size_t)r1 * F_DIM + col;
                float t2 = accT[mt][nt][2], t3 = accT[mt][nt][3];
                *(__half2*)&g_t16[o] = __floats2half2_rn(t2, t3);
                *(float2*)&out[o] = make_float2(t2 + accP[mt][nt][2] + b0,
                                                t3 + accP[mt][nt][3] + b1);
            }
        }
    }
}

// ---------------------------------------------------------------------------
// Kernel 2: gather-min over fp16 t. One warp per node; lane owns 2 features
// (one half2) -> warp reads 128 B per neighbor row. 32-bit offset math.
// Index dtype (int64 vs int32) detected per-warp via ballot on first 32 words.
// ---------------------------------------------------------------------------
__global__ __launch_bounds__(256)
void gather_min_kernel(const void* __restrict__ nbr_raw,
                       float* __restrict__ out,
                       int n, int K)
{
    const int lane = threadIdx.x & 31;

    unsigned int probe = ((const unsigned int*)nbr_raw)[lane];
    bool oddzero = ((lane & 1) == 0) || (probe == 0u);
    const bool is64 = (__ballot_sync(0xFFFFFFFFu, oddzero) == 0xFFFFFFFFu);

    int w = (int)((blockIdx.x * (long long)blockDim.x + threadIdx.x) >> 5);
    if (w >= n) return;

    const __half2* t2 = (const __half2*)g_t16;
    __half2 m = __float2half2_rn(65504.f);

    if (K == 16) {
        int u[16];
        if (is64) {
            const longlong2* nb = (const longlong2*)((const long long*)nbr_raw
                                                     + (size_t)w * 16);
#pragma unroll
            for (int j = 0; j < 8; j++) {
                longlong2 p = __ldg(&nb[j]);
                u[2 * j]     = (int)p.x;
                u[2 * j + 1] = (int)p.y;
            }
        } else {
            const int4* nb = (const int4*)((const int*)nbr_raw + (size_t)w * 16);
#pragma unroll
            for (int j = 0; j < 4; j++) {
                int4 p = __ldg(&nb[j]);
                u[4 * j]     = p.x;
                u[4 * j + 1] = p.y;
                u[4 * j + 2] = p.z;
                u[4 * j + 3] = p.w;
            }
        }
#pragma unroll
        for (int j = 0; j < 16; j++) {
            __half2 v = __ldg(&t2[u[j] * 32 + lane]);
            m = __hmin2(m, v);
        }
    } else {
        for (int j = 0; j < K; j++) {
            int u = is64 ? (int)((const long long*)nbr_raw)[(size_t)w * K + j]
                         : ((const int*)nbr_raw)[(size_t)w * K + j];
            __half2 v = __ldg(&t2[u * 32 + lane]);
            m = __hmin2(m, v);
        }
    }

    float2 mf = __half22float2(m);
    float2* out2 = (float2*)out;
    size_t o = (size_t)w * 32 + lane;
    float2 b = out2[o];
    b.x -= mf.x;
    b.y -= mf.y;
    out2[o] = b;
}

// ============================== launch =====================================
extern "C" void kernel_launch(void* const* d_in, const int* in_sizes, int n_in,
                              void* d_out, int out_size)
{
    const float* feat    = (const float*)d_in[0];
    const void*  nbr     = d_in[1];
    const float* theta_w = (const float*)d_in[2];
    const float* theta_b = (const float*)d_in[3];
    const float* phi_w   = (const float*)d_in[4];
    const float* phi_b   = (const float*)d_in[5];
    float* out = (float*)d_out;

    const int n = in_sizes[0] / F_DIM;     // number of nodes
    const int K = in_sizes[1] / n;         // neighbors per node (=16)

    static int smem_set = 0;
    if (!smem_set) {
        cudaFuncSetAttribute(gemm_mma_kernel,
                             cudaFuncAttributeMaxDynamicSharedMemorySize,
                             SM_BYTES);
        smem_set = 1;
    }

    int g1 = (n + 63) / 64;
    gemm_mma_kernel<<<g1, 256, SM_BYTES>>>(feat, theta_w, theta_b, phi_w,
                                           phi_b, out, n);

    long long total_threads = (long long)n * 32;
    int g2 = (int)((total_threads + 255) / 256);
    gather_min_kernel<<<g2, 256>>>(nbr, out, n, K);
}

// round 9
// speedup vs baseline: 1.8374x; 1.1810x over previous
#include <cuda_runtime.h>
#include <cuda_fp16.h>
#include <cstdint>

// ---------------------------------------------------------------------------
// EdgeConv (mlp_layer=0, aggregate=max), restructured:
//   t      = feat @ theta_w                      [N, 64]
//   base   = t + feat @ phi_w + theta_b + phi_b  [N, 64]   (written to d_out)
//   out[v] = base[v] - min_k t[nbr[v,k]]         (per-feature min)
//
// GEMM: mma.sync m16n8k16 fp16, 2-pass A split (t ~= (Ahi+Alo)*Bhi).
// B pre-converted ONCE to fp16 [n][k] by a prep kernel -> GEMM stages it
// with coalesced uint4 copies and ldmatrix (no per-CTA conversion).
// Gather: fp16 t, 2 nodes per warp (uint2 lanes + shfl-broadcast indices).
// ---------------------------------------------------------------------------

#define F_DIM 64
#define N_MAX 120000

__device__ __half g_t16[(size_t)N_MAX * F_DIM];   // fp16 t for the gather
__device__ __half g_Bh[128 * 64];                 // fp16 [nrow][k]; nrow<64
                                                  // theta col, >=64 phi col

// ============================= PTX helpers =================================
__device__ __forceinline__ uint32_t smem_u32(const void* p) {
    uint32_t a;
    asm("{ .reg .u64 tmp; cvta.to.shared.u64 tmp, %1; cvt.u32.u64 %0, tmp; }"
        : "=r"(a) : "l"(p));
    return a;
}

__device__ __forceinline__ void ldsm_x4(uint32_t* r, uint32_t addr) {
    asm volatile("ldmatrix.sync.aligned.m8n8.x4.shared.b16 {%0,%1,%2,%3}, [%4];"
                 : "=r"(r[0]), "=r"(r[1]), "=r"(r[2]), "=r"(r[3]) : "r"(addr));
}

__device__ __forceinline__ void mma16816(float* c, const uint32_t* a,
                                         const uint32_t* b) {
    asm volatile(
        "mma.sync.aligned.m16n8k16.row.col.f32.f16.f16.f32 "
        "{%0,%1,%2,%3}, {%4,%5,%6,%7}, {%8,%9}, {%0,%1,%2,%3};"
        : "+f"(c[0]), "+f"(c[1]), "+f"(c[2]), "+f"(c[3])
        : "r"(a[0]), "r"(a[1]), "r"(a[2]), "r"(a[3]), "r"(b[0]), "r"(b[1]));
}

// fp16 hi/lo split of two floats -> packed hi word + lo word
__device__ __forceinline__ uint32_t pack_hilo(float x, float y,
                                              uint32_t& lo_out) {
    __half hx = __float2half_rn(x);
    __half hy = __float2half_rn(y);
    __half lx = __float2half_rn(x - __half2float(hx));
    __half ly = __float2half_rn(y - __half2float(hy));
    lo_out = (uint32_t)__half_as_ushort(lx) |
             ((uint32_t)__half_as_ushort(ly) << 16);
    return (uint32_t)__half_as_ushort(hx) |
           ((uint32_t)__half_as_ushort(hy) << 16);
}

// SMEM layout (dynamic, bytes). Rows padded to 72 fp16 = 144 B (ldmatrix
// conflict-free: 8 rows x 144 B hit 8 distinct 16B bank groups).
#define SM_AH 0
#define SM_AL 9216
#define SM_BH 18432
#define SM_BYTES 36864

// ============================ prep kernel ==================================
// One-off: g_Bh[nrow][k] = fp16(w[k][nrow&63]); nrow<64 theta, >=64 phi.
__global__ void prep_b_kernel(const float* __restrict__ theta_w,
                              const float* __restrict__ phi_w)
{
    int idx = blockIdx.x * blockDim.x + threadIdx.x;   // 0..8191
    if (idx < 8192) {
        int k = idx >> 7;          // 0..63
        int c = idx & 127;         // 0..127 (coalesced read dim)
        const float* w = (c < 64) ? theta_w : phi_w;
        float v = w[k * F_DIM + (c & 63)];
        g_Bh[c * 64 + k] = __float2half_rn(v);
    }
}

// ============================ GEMM kernel ==================================
// CTA: 64 rows x full N=128 ([theta|phi]). 8 warps: wm=(wid&1)*32,
// wn=(wid>>1)*16. Warp owns theta cols wn..wn+15 and phi cols 64+wn..64+wn+15
// -> t and base combine in registers.
__global__ __launch_bounds__(256, 4)
void gemm_mma_kernel(const float* __restrict__ feat,
                     const float* __restrict__ theta_b,
                     const float* __restrict__ phi_b,
                     float* __restrict__ out,
                     int n)
{
    extern __shared__ char sm[];
    const uint32_t sbase = smem_u32(sm);
    const int tid = threadIdx.x;
    const int rb  = blockIdx.x * 64;

    // ---- stage A: feat[rb..rb+63][0..63] -> fp16 hi/lo (coalesced f4) -----
#pragma unroll
    for (int p = 0; p < 4; p++) {
        int idx = tid + p * 256;         // 0..1023
        int c4  = idx & 15;              // float4 column group
        int row = idx >> 4;              // 0..63
        float4 f = make_float4(0.f, 0.f, 0.f, 0.f);
        int gr = rb + row;
        if (gr < n) f = *(const float4*)&feat[(size_t)gr * F_DIM + c4 * 4];
        uint32_t l0, l1;
        uint32_t h0 = pack_hilo(f.x, f.y, l0);
        uint32_t h1 = pack_hilo(f.z, f.w, l1);
        uint32_t off = row * 144 + c4 * 8;
        *(uint2*)(sm + SM_AH + off) = make_uint2(h0, h1);
        *(uint2*)(sm + SM_AL + off) = make_uint2(l0, l1);
    }

    // ---- stage B: copy pre-converted fp16 tile (coalesced uint4) ----------
    {
        const __half* gB = g_Bh;
#pragma unroll
        for (int p = 0; p < 4; p++) {
            int idx  = tid + p * 256;    // 0..1023
            int nrow = idx >> 3;         // 0..127
            int c8   = idx & 7;          // 16-byte chunk
            uint4 v = *(const uint4*)&gB[nrow * 64 + c8 * 8];
            *(uint4*)(sm + SM_BH + nrow * 144 + c8 * 16) = v;
        }
    }
    __syncthreads();

    const int wid  = tid >> 5;
    const int lane = tid & 31;
    const int wm   = (wid & 1) * 32;
    const int wn   = (wid >> 1) * 16;
    const int li   = lane & 7;
    const int lg   = lane >> 3;

    float accT[2][2][4], accP[2][2][4];
#pragma unroll
    for (int mt = 0; mt < 2; mt++)
#pragma unroll
        for (int nt = 0; nt < 2; nt++)
#pragma unroll
            for (int j = 0; j < 4; j++) {
                accT[mt][nt][j] = 0.f;
                accP[mt][nt][j] = 0.f;
            }

#pragma unroll
    for (int ks = 0; ks < 4; ks++) {
        const int k0 = ks * 16;
        // ---- B fragments via ldmatrix (loaded once, shared by both passes)
        uint32_t bT[2][2], bP[2][2];
        {
            int row = wn + li + (lg >> 1) * 8;
            int col = k0 + (lg & 1) * 8;
            uint32_t r[4];
            ldsm_x4(r, sbase + SM_BH + row * 144 + col * 2);
            bT[0][0] = r[0]; bT[0][1] = r[1];
            bT[1][0] = r[2]; bT[1][1] = r[3];
            ldsm_x4(r, sbase + SM_BH + (64 + row) * 144 + col * 2);
            bP[0][0] = r[0]; bP[0][1] = r[1];
            bP[1][0] = r[2]; bP[1][1] = r[3];
        }
        // ---- two A passes (hi, lo) share the B fragments -------------------
#pragma unroll
        for (int p = 0; p < 2; p++) {
            const uint32_t aoff = p ? SM_AL : SM_AH;
            uint32_t a[2][4];
#pragma unroll
            for (int mt = 0; mt < 2; mt++) {
                int row = wm + mt * 16 + li + (lg & 1) * 8;
                int col = k0 + (lg >> 1) * 8;
                ldsm_x4(a[mt], sbase + aoff + row * 144 + col * 2);
            }
#pragma unroll
            for (int mt = 0; mt < 2; mt++)
#pragma unroll
                for (int nt = 0; nt < 2; nt++) {
                    mma16816(accT[mt][nt], a[mt], bT[nt]);
                    mma16816(accP[mt][nt], a[mt], bP[nt]);
                }
        }
    }

    // ---- epilogue: direct register combine + store -------------------------
#pragma unroll
    for (int mt = 0; mt < 2; mt++) {
        int r0 = rb + wm + mt * 16 + (lane >> 2);
#pragma unroll
        for (int nt = 0; nt < 2; nt++) {
            int col = wn + nt * 8 + 2 * (lane & 3);
            float b0 = theta_b[col]     + phi_b[col];
            float b1 = theta_b[col + 1] + phi_b[col + 1];
            if (r0 < n) {
                size_t o = (size_t)r0 * F_DIM + col;
                float t0 = accT[mt][nt][0], t1 = accT[mt][nt][1];
                *(__half2*)&g_t16[o] = __floats2half2_rn(t0, t1);
                *(float2*)&out[o] = make_float2(t0 + accP[mt][nt][0] + b0,
                                                t1 + accP[mt][nt][1] + b1);
            }
            int r1 = r0 + 8;
            if (r1 < n) {
                size_t o = (size_t)r1 * F_DIM + col;
                float t2 = accT[mt][nt][2], t3 = accT[mt][nt][3];
                *(__half2*)&g_t16[o] = __floats2half2_rn(t2, t3);
                *(float2*)&out[o] = make_float2(t2 + accP[mt][nt][2] + b0,
                                                t3 + accP[mt][nt][3] + b1);
            }
        }
    }
}

// ---------------------------------------------------------------------------
// Kernel 2: gather-min over fp16 t. TWO nodes per warp: lanes 0-15 -> node
// 2w, lanes 16-31 -> node 2w+1. Lane hl (0..15) owns uint2 chunk hl of the
// 128-B row (features 4hl..4hl+3). Indices: one coalesced load per lane,
// broadcast via shfl(width=16). Epilogue is a float4 read-modify-write.
// ---------------------------------------------------------------------------
__global__ __launch_bounds__(256)
void gather_min_kernel(const void* __restrict__ nbr_raw,
                       float* __restrict__ out,
                       int n, int K)
{
    const int lane = threadIdx.x & 31;

    // dtype detect (uniform): int64 indices < 2^31 have zero odd words
    unsigned int probe = ((const unsigned int*)nbr_raw)[lane];
    bool oddzero = ((lane & 1) == 0) || (probe == 0u);
    const bool is64 = (__ballot_sync(0xFFFFFFFFu, oddzero) == 0xFFFFFFFFu);

    long long wpair = (blockIdx.x * (long long)blockDim.x + threadIdx.x) >> 5;
    const int half = lane >> 4;      // 0 or 1
    const int hl   = lane & 15;      // chunk within row
    int node = (int)(wpair * 2) + half;
    if ((int)(wpair * 2) >= n) return;
    if (node >= n) node = n - 1;     // duplicate work on odd tail (benign)

    // my neighbor index (lane hl holds neighbor hl of my node)
    int myidx;
    if (K == 16) {
        myidx = is64 ? (int)((const long long*)nbr_raw)[(size_t)node * 16 + hl]
                     : ((const int*)nbr_raw)[(size_t)node * 16 + hl];
    } else {
        myidx = 0;
    }

    const uint2* tp = (const uint2*)g_t16;   // 16 uint2 per row
    __half2 m0 = __float2half2_rn(65504.f);
    __half2 m1 = m0;

    if (K == 16) {
#pragma unroll
        for (int j = 0; j < 16; j++) {
            int uj = __shfl_sync(0xFFFFFFFFu, myidx, j, 16);
            uint2 v = __ldg(&tp[uj * 16 + hl]);
            m0 = __hmin2(m0, *(__half2*)&v.x);
            m1 = __hmin2(m1, *(__half2*)&v.y);
        }
    } else {
        for (int j = 0; j < K; j++) {
            int uj = is64 ? (int)((const long long*)nbr_raw)[(size_t)node * K + j]
                          : ((const int*)nbr_raw)[(size_t)node * K + j];
            uint2 v = __ldg(&tp[uj * 16 + hl]);
            m0 = __hmin2(m0, *(__half2*)&v.x);
            m1 = __hmin2(m1, *(__half2*)&v.y);
        }
    }

    float2 f0 = __half22float2(m0);
    float2 f1 = __half22float2(m1);
    float4* out4 = (float4*)out;
    size_t o = (size_t)node * 16 + hl;       // 16 float4 per row
    float4 b = out4[o];
    b.x -= f0.x;
    b.y -= f0.y;
    b.z -= f1.x;
    b.w -= f1.y;
    out4[o] = b;
}

// ============================== launch =====================================
extern "C" void kernel_launch(void* const* d_in, const int* in_sizes, int n_in,
                              void* d_out, int out_size)
{
    const float* feat    = (const float*)d_in[0];
    const void*  nbr     = d_in[1];
    const float* theta_w = (const float*)d_in[2];
    const float* theta_b = (const float*)d_in[3];
    const float* phi_w   = (const float*)d_in[4];
    const float* phi_b   = (const float*)d_in[5];
    float* out = (float*)d_out;

    const int n = in_sizes[0] / F_DIM;     // number of nodes
    const int K = in_sizes[1] / n;         // neighbors per node (=16)

    static int smem_set = 0;
    if (!smem_set) {
        cudaFuncSetAttribute(gemm_mma_kernel,
                             cudaFuncAttributeMaxDynamicSharedMemorySize,
                             SM_BYTES);
        smem_set = 1;
    }

    prep_b_kernel<<<32, 256>>>(theta_w, phi_w);

    int g1 = (n + 63) / 64;
    gemm_mma_kernel<<<g1, 256, SM_BYTES>>>(feat, theta_b, phi_b, out, n);

    long long pairs = ((long long)n + 1) / 2;        // 2 nodes per warp
    long long total_threads = pairs * 32;
    int g2 = (int)((total_threads + 255) / 256);
    gather_min_kernel<<<g2, 256>>>(nbr, out, n, K);
}